// round 12
// baseline (speedup 1.0000x reference)
#include <cuda_runtime.h>
#include <math.h>

#define M_   24
#define TS_  60
#define NX_  192
#define NY_  192
#define NG_  50
#define T_   50
#define HD_  32   // H*D
#define H_   4
#define D_   8

// Compact tables: setup_kernel -> gather_kernel (~14 KB)
__device__ float g_e0[M_ * NG_];     // w*my*(1-fy)
__device__ float g_e1[M_ * NG_];     // w*my*fy
__device__ short g_iy[M_ * NG_];
__device__ unsigned char g_ti[T_ * M_];
__device__ int   g_ix[NG_];
__device__ float g_fx[NG_];
__device__ float g_mx[NG_];

// jnp.linspace(0,100,192): delta = 100/191 (f32), endpoint forced exact.
__device__ __forceinline__ float gridx(int k) {
    return (k == NX_ - 1) ? 100.0f : (float)k * (100.0f / 191.0f);
}

__global__ __launch_bounds__(1024)
void setup_kernel(const float* __restrict__ params,
                  const float* __restrict__ src_y,
                  const float* __restrict__ stl,
                  const float* __restrict__ Wq,
                  const float* __restrict__ bq,
                  const float* __restrict__ Wk,
                  const float* __restrict__ bk,
                  const float* __restrict__ lyt_p,
                  const float* __restrict__ cut_p,
                  const float* __restrict__ nit_p)
{
    __shared__ __align__(16) float s_y[M_ * NY_];
    __shared__ float s_Wq[3*HD_], s_Wk[3*HD_], s_bq[HD_], s_bk[HD_], s_Q[HD_];
    __shared__ float s_ly[M_], s_cu[M_], s_ni[M_], s_scale[M_];
    __shared__ float s_logits[M_][H_];
    __shared__ float s_sm[H_][M_];
    __shared__ float s_w[M_];

    const int tid = threadIdx.x;
    const float lyt = __ldg(lyt_p);
    const float t_ly = (lyt - 30.0f) / 90.0f;
    const float t_cu = __ldg(cut_p) / 0.0029f;
    const float t_ni = __ldg(nit_p) / 0.0018f;

    // ---- phase 0: stage inputs, maximum MLP ----
    {
        const float4* sy4 = reinterpret_cast<const float4*>(src_y);
        float4* dy4 = reinterpret_cast<float4*>(s_y);
        for (int p = tid; p < (M_ * NY_) / 4; p += 1024)
            dy4[p] = __ldg(sy4 + p);
    }
    if (tid < 3 * HD_) { s_Wq[tid] = __ldg(Wq + tid); s_Wk[tid] = __ldg(Wk + tid); }
    else if (tid >= 128 && tid < 128 + HD_) {
        int k = tid - 128;
        s_bq[k] = __ldg(bq + k); s_bk[k] = __ldg(bk + k);
    }
    else if (tid >= 192 && tid < 192 + M_) {
        int m = tid - 192;
        float lys = __ldg(params + 3*m + 0);
        s_ly[m] = (lys - 30.0f) / 90.0f;
        s_cu[m] = __ldg(params + 3*m + 1) / 0.0029f;
        s_ni[m] = __ldg(params + 3*m + 2) / 0.0018f;
        s_scale[m] = lyt / lys;
    }
    __syncthreads();

    // ---- phase 1: Q vector ----
    if (tid < HD_)
        s_Q[tid] = t_ly*s_Wq[tid] + t_cu*s_Wq[HD_+tid] + t_ni*s_Wq[2*HD_+tid] + s_bq[tid];
    __syncthreads();

    // ---- phase 2: logits (m,h) ----
    if (tid < M_ * H_) {
        int m = tid / H_, h = tid % H_;
        float acc = 0.0f;
        #pragma unroll
        for (int d = 0; d < D_; d++) {
            int k = h*D_ + d;
            float Kv = s_ly[m]*s_Wk[k] + s_cu[m]*s_Wk[HD_+k] + s_ni[m]*s_Wk[2*HD_+k] + s_bk[k];
            acc += Kv * s_Q[k];
        }
        s_logits[m][h] = acc * (1.0f / sqrtf((float)D_));
    }
    __syncthreads();

    // ---- phase 3: softmax per head (4 threads, serial over 24) ----
    if (tid < H_) {
        int h = tid;
        float mx = -1e30f;
        for (int m = 0; m < M_; m++) mx = fmaxf(mx, s_logits[m][h]);
        float s = 0.0f;
        for (int m = 0; m < M_; m++) s += expf(s_logits[m][h] - mx);
        for (int m = 0; m < M_; m++) s_sm[h][m] = expf(s_logits[m][h] - mx) / s;
    }
    __syncthreads();

    // ---- phase 4: weights, warp 0 only, shfl reductions ----
    if (tid < 32) {
        int m = tid;
        float swv = 0.0f, attn = 0.0f;
        if (m < M_) {
            float d2 = ((s_ly[m]-t_ly)*(s_ly[m]-t_ly) +
                        (s_cu[m]-t_cu)*(s_cu[m]-t_cu) +
                        (s_ni[m]-t_ni)*(s_ni[m]-t_ni)) / (0.2f*0.2f);
            swv = expf(-d2 * 0.5f);
            attn = (s_sm[0][m] + s_sm[1][m] + s_sm[2][m] + s_sm[3][m]) * 0.25f;
        }
        float ssum = swv;
        #pragma unroll
        for (int o = 16; o > 0; o >>= 1) ssum += __shfl_xor_sync(0xffffffff, ssum, o);
        float wa = attn * (swv / (ssum + 1e-12f));
        float wsum = wa;
        #pragma unroll
        for (int o = 16; o > 0; o >>= 1) wsum += __shfl_xor_sync(0xffffffff, wsum, o);
        if (m < M_) s_w[m] = wa / (wsum + 1e-12f);
    }
    __syncthreads();

    // ---- phase 5: all tables in parallel ----
    // x-axis
    if (tid >= 512 && tid < 512 + NG_) {
        int i = tid - 512;
        float q = (i == NG_-1) ? 100.0f : (float)i * (100.0f / 49.0f);
        int lo = 0, hi = NX_;
        while (lo < hi) { int mid = (lo + hi) >> 1; if (gridx(mid) <= q) lo = mid + 1; else hi = mid; }
        int idx = min(max(lo - 1, 0), NX_ - 2);
        float g0 = gridx(idx), g1 = gridx(idx + 1);
        g_ix[i] = idx;
        g_fx[i] = (q - g0) / (g1 - g0);
        g_mx[i] = (q >= 0.0f && q <= 100.0f) ? 1.0f : 0.0f;
    }
    // time indices (round-half-even)
    if (tid >= 576 && tid < 576 + 400) {
        for (int p = tid - 576; p < T_ * M_; p += 400) {
            int t = p / M_, m = p % M_;
            float tv = (t == T_-1) ? 200.0f : (float)t * (200.0f / 49.0f);
            float r = rintf(tv / __ldg(stl + m) * (float)(TS_ - 1));
            g_ti[t * M_ + m] = (unsigned char)min(max((int)r, 0), TS_ - 1);
        }
    }
    // y-axis: binary search in shared (1200 searches over 512 threads)
    if (tid < 512) {
        for (int p = tid; p < M_ * NG_; p += 512) {
            int m = p / NG_, j = p % NG_;
            float q  = (float)j / 49.0f * lyt;
            float sc = s_scale[m];
            const float* ys = s_y + m * NY_;
            int lo = 0, hi = NY_;
            while (lo < hi) { int mid = (lo + hi) >> 1; if (ys[mid]*sc <= q) lo = mid + 1; else hi = mid; }
            int idx = min(max(lo - 1, 0), NY_ - 2);
            float gy0 = ys[idx] * sc, gy1 = ys[idx + 1] * sc;
            float fy = (q - gy0) / (gy1 - gy0);
            float inb = (q >= ys[0]*sc && q <= ys[NY_-1]*sc) ? 1.0f : 0.0f;
            float wm = s_w[m] * inb;
            g_iy[p] = (short)idx;
            g_e0[p] = wm * (1.0f - fy);
            g_e1[p] = wm * fy;
        }
    }
}

__global__ __launch_bounds__(256)
void gather_kernel(const float* __restrict__ c1,
                   const float* __restrict__ c2,
                   const float* __restrict__ cut_p,
                   const float* __restrict__ nit_p,
                   float* __restrict__ out)
{
    __shared__ float s_e0[M_ * NG_];
    __shared__ float s_e1[M_ * NG_];
    __shared__ short s_iy[M_ * NG_];
    __shared__ unsigned char s_ti[T_ * M_];
    __shared__ int   s_ix[NG_];
    __shared__ float s_fx[NG_];
    __shared__ float s_mx[NG_];

    const int tid = threadIdx.x;
    for (int p = tid; p < M_ * NG_; p += 256) {
        s_e0[p] = g_e0[p];
        s_e1[p] = g_e1[p];
        s_iy[p] = g_iy[p];
        s_ti[p] = g_ti[p];          // T_*M_ == M_*NG_ == 1200
    }
    if (tid < NG_) { s_ix[tid] = g_ix[tid]; s_fx[tid] = g_fx[tid]; s_mx[tid] = g_mx[tid]; }
    __syncthreads();

    const int gidx = blockIdx.x * 256 + tid;
    const int nthreads = 2 * T_ * NG_ * NG_;   // 250000
    if (gidx >= nthreads) return;

    const int j = gidx % NG_;
    const int i = (gidx / NG_) % NG_;
    const int t = (gidx / (NG_ * NG_)) % T_;
    const int f = gidx / (T_ * NG_ * NG_);

    const float* __restrict__ base = f ? c2 : c1;
    const int   ixN = s_ix[i] * NY_;
    const float fx  = s_fx[i];
    const float fx1 = 1.0f - fx;

    float acc = 0.0f;
    // software pipeline: groups of 6 members, 24 LDGs in flight per group
    #pragma unroll
    for (int g = 0; g < M_ / 6; g++) {
        float a00[6], a01[6], a10[6], a11[6], e0[6], e1[6];
        #pragma unroll
        for (int u = 0; u < 6; u++) {
            const int m = g * 6 + u;
            const int iy = s_iy[m * NG_ + j];
            e0[u] = s_e0[m * NG_ + j];
            e1[u] = s_e1[m * NG_ + j];
            const float* __restrict__ p0 =
                base + (m * TS_ + (int)s_ti[t * M_ + m]) * (NX_*NY_) + ixN + iy;
            a00[u] = __ldg(p0);
            a01[u] = __ldg(p0 + 1);
            a10[u] = __ldg(p0 + NY_);
            a11[u] = __ldg(p0 + NY_ + 1);
        }
        #pragma unroll
        for (int u = 0; u < 6; u++)
            acc += (a00[u] * fx1 + a10[u] * fx) * e0[u]
                 + (a01[u] * fx1 + a11[u] * fx) * e1[u];
    }
    float v = acc * s_mx[i];
    if (f == 0 && j == 0)       v = __ldg(cut_p);
    if (f == 1 && j == NG_ - 1) v = __ldg(nit_p);

    out[gidx] = v;
}

extern "C" void kernel_launch(void* const* d_in, const int* in_sizes, int n_in,
                              void* d_out, int out_size)
{
    const float* c1    = (const float*)d_in[0];
    const float* c2    = (const float*)d_in[1];
    const float* params= (const float*)d_in[2];
    const float* src_y = (const float*)d_in[3];
    const float* stl   = (const float*)d_in[4];
    const float* Wq    = (const float*)d_in[5];
    const float* bq    = (const float*)d_in[6];
    const float* Wk    = (const float*)d_in[7];
    const float* bk    = (const float*)d_in[8];
    const float* lyt   = (const float*)d_in[9];
    const float* cut   = (const float*)d_in[10];
    const float* nit   = (const float*)d_in[11];
    float* out = (float*)d_out;

    setup_kernel<<<1, 1024>>>(params, src_y, stl, Wq, bq, Wk, bk, lyt, cut, nit);

    const int threads = 2 * T_ * NG_ * NG_;   // 250000
    gather_kernel<<<(threads + 255) / 256, 256>>>(c1, c2, cut, nit, out);
}

// round 14
// speedup vs baseline: 1.1008x; 1.1008x over previous
#include <cuda_runtime.h>
#include <math.h>

#define M_   24
#define TS_  60
#define NX_  192
#define NY_  192
#define NG_  50
#define T_   50
#define HD_  32   // H*D
#define H_   4
#define D_   8

// Compact tables: setup_kernel -> gather_kernel (~14 KB)
__device__ float g_e0[M_ * NG_];     // w*my*(1-fy)
__device__ float g_e1[M_ * NG_];     // w*my*fy
__device__ short g_iy[M_ * NG_];
__device__ unsigned char g_ti[T_ * M_];
__device__ int   g_ix[NG_];
__device__ float g_fx[NG_];
__device__ float g_mx[NG_];

// jnp.linspace(0,100,192): delta = 100/191 (f32), endpoint forced exact.
__device__ __forceinline__ float gridx(int k) {
    return (k == NX_ - 1) ? 100.0f : (float)k * (100.0f / 191.0f);
}

__global__ __launch_bounds__(1024)
void setup_kernel(const float* __restrict__ params,
                  const float* __restrict__ src_y,
                  const float* __restrict__ stl,
                  const float* __restrict__ Wq,
                  const float* __restrict__ bq,
                  const float* __restrict__ Wk,
                  const float* __restrict__ bk,
                  const float* __restrict__ lyt_p,
                  const float* __restrict__ cut_p,
                  const float* __restrict__ nit_p)
{
    __shared__ __align__(16) float s_y[M_ * NY_];
    __shared__ float s_Wq[3*HD_], s_Wk[3*HD_], s_bq[HD_], s_bk[HD_], s_Q[HD_];
    __shared__ float s_ly[M_], s_cu[M_], s_ni[M_], s_scale[M_];
    __shared__ float s_logits[M_][H_];
    __shared__ float s_sm[H_][M_];
    __shared__ float s_w[M_];

    const int tid = threadIdx.x;
    const float lyt = __ldg(lyt_p);
    const float t_ly = (lyt - 30.0f) / 90.0f;
    const float t_cu = __ldg(cut_p) / 0.0029f;
    const float t_ni = __ldg(nit_p) / 0.0018f;

    // ---- phase 0: stage inputs, maximum MLP ----
    {
        const float4* sy4 = reinterpret_cast<const float4*>(src_y);
        float4* dy4 = reinterpret_cast<float4*>(s_y);
        for (int p = tid; p < (M_ * NY_) / 4; p += 1024)
            dy4[p] = __ldg(sy4 + p);
    }
    if (tid < 3 * HD_) { s_Wq[tid] = __ldg(Wq + tid); s_Wk[tid] = __ldg(Wk + tid); }
    else if (tid >= 128 && tid < 128 + HD_) {
        int k = tid - 128;
        s_bq[k] = __ldg(bq + k); s_bk[k] = __ldg(bk + k);
    }
    else if (tid >= 192 && tid < 192 + M_) {
        int m = tid - 192;
        float lys = __ldg(params + 3*m + 0);
        s_ly[m] = (lys - 30.0f) / 90.0f;
        s_cu[m] = __ldg(params + 3*m + 1) / 0.0029f;
        s_ni[m] = __ldg(params + 3*m + 2) / 0.0018f;
        s_scale[m] = lyt / lys;
    }
    __syncthreads();

    // ---- phase 1: Q vector ----
    if (tid < HD_)
        s_Q[tid] = t_ly*s_Wq[tid] + t_cu*s_Wq[HD_+tid] + t_ni*s_Wq[2*HD_+tid] + s_bq[tid];
    __syncthreads();

    // ---- phase 2: logits (m,h) ----
    if (tid < M_ * H_) {
        int m = tid / H_, h = tid % H_;
        float acc = 0.0f;
        #pragma unroll
        for (int d = 0; d < D_; d++) {
            int k = h*D_ + d;
            float Kv = s_ly[m]*s_Wk[k] + s_cu[m]*s_Wk[HD_+k] + s_ni[m]*s_Wk[2*HD_+k] + s_bk[k];
            acc += Kv * s_Q[k];
        }
        s_logits[m][h] = acc * (1.0f / sqrtf((float)D_));
    }
    __syncthreads();

    // ---- phase 3: softmax per head ----
    if (tid < H_) {
        int h = tid;
        float mx = -1e30f;
        for (int m = 0; m < M_; m++) mx = fmaxf(mx, s_logits[m][h]);
        float s = 0.0f;
        for (int m = 0; m < M_; m++) s += expf(s_logits[m][h] - mx);
        for (int m = 0; m < M_; m++) s_sm[h][m] = expf(s_logits[m][h] - mx) / s;
    }
    __syncthreads();

    // ---- phase 4: weights, warp 0 shfl reductions ----
    if (tid < 32) {
        int m = tid;
        float swv = 0.0f, attn = 0.0f;
        if (m < M_) {
            float d2 = ((s_ly[m]-t_ly)*(s_ly[m]-t_ly) +
                        (s_cu[m]-t_cu)*(s_cu[m]-t_cu) +
                        (s_ni[m]-t_ni)*(s_ni[m]-t_ni)) / (0.2f*0.2f);
            swv = expf(-d2 * 0.5f);
            attn = (s_sm[0][m] + s_sm[1][m] + s_sm[2][m] + s_sm[3][m]) * 0.25f;
        }
        float ssum = swv;
        #pragma unroll
        for (int o = 16; o > 0; o >>= 1) ssum += __shfl_xor_sync(0xffffffff, ssum, o);
        float wa = attn * (swv / (ssum + 1e-12f));
        float wsum = wa;
        #pragma unroll
        for (int o = 16; o > 0; o >>= 1) wsum += __shfl_xor_sync(0xffffffff, wsum, o);
        if (m < M_) s_w[m] = wa / (wsum + 1e-12f);
    }
    __syncthreads();

    // ---- phase 5: all tables in parallel ----
    if (tid >= 512 && tid < 512 + NG_) {
        int i = tid - 512;
        float q = (i == NG_-1) ? 100.0f : (float)i * (100.0f / 49.0f);
        int lo = 0, hi = NX_;
        while (lo < hi) { int mid = (lo + hi) >> 1; if (gridx(mid) <= q) lo = mid + 1; else hi = mid; }
        int idx = min(max(lo - 1, 0), NX_ - 2);
        float g0 = gridx(idx), g1 = gridx(idx + 1);
        g_ix[i] = idx;
        g_fx[i] = (q - g0) / (g1 - g0);
        g_mx[i] = (q >= 0.0f && q <= 100.0f) ? 1.0f : 0.0f;
    }
    if (tid >= 576 && tid < 576 + 400) {
        for (int p = tid - 576; p < T_ * M_; p += 400) {
            int t = p / M_, m = p % M_;
            float tv = (t == T_-1) ? 200.0f : (float)t * (200.0f / 49.0f);
            float r = rintf(tv / __ldg(stl + m) * (float)(TS_ - 1));
            g_ti[t * M_ + m] = (unsigned char)min(max((int)r, 0), TS_ - 1);
        }
    }
    if (tid < 512) {
        for (int p = tid; p < M_ * NG_; p += 512) {
            int m = p / NG_, j = p % NG_;
            float q  = (float)j / 49.0f * lyt;
            float sc = s_scale[m];
            const float* ys = s_y + m * NY_;
            int lo = 0, hi = NY_;
            while (lo < hi) { int mid = (lo + hi) >> 1; if (ys[mid]*sc <= q) lo = mid + 1; else hi = mid; }
            int idx = min(max(lo - 1, 0), NY_ - 2);
            float gy0 = ys[idx] * sc, gy1 = ys[idx + 1] * sc;
            float fy = (q - gy0) / (gy1 - gy0);
            float inb = (q >= ys[0]*sc && q <= ys[NY_-1]*sc) ? 1.0f : 0.0f;
            float wm = s_w[m] * inb;
            g_iy[p] = (short)idx;
            g_e0[p] = wm * (1.0f - fy);
            g_e1[p] = wm * fy;
        }
    }
}

// Split-m gather: 2 threads per output (m 0-11 / m 12-23), smem combine.
// __launch_bounds__(256, 8) caps regs at 32 -> 8 blocks/SM = 64 warps (full).
__global__ __launch_bounds__(256, 8)
void gather_kernel(const float* __restrict__ c1,
                   const float* __restrict__ c2,
                   const float* __restrict__ cut_p,
                   const float* __restrict__ nit_p,
                   float* __restrict__ out)
{
    __shared__ float s_e0[M_ * NG_];
    __shared__ float s_e1[M_ * NG_];
    __shared__ short s_iy[M_ * NG_];
    __shared__ unsigned char s_ti[T_ * M_];
    __shared__ int   s_ix[NG_];
    __shared__ float s_fx[NG_];
    __shared__ float s_mx[NG_];
    __shared__ float s_part[128];

    const int tid = threadIdx.x;
    for (int p = tid; p < M_ * NG_; p += 256) {
        s_e0[p] = g_e0[p];
        s_e1[p] = g_e1[p];
        s_iy[p] = g_iy[p];
        s_ti[p] = g_ti[p];          // T_*M_ == M_*NG_ == 1200
    }
    if (tid < NG_) { s_ix[tid] = g_ix[tid]; s_fx[tid] = g_fx[tid]; s_mx[tid] = g_mx[tid]; }
    __syncthreads();

    const int out_local = tid & 127;           // 0..127: output within block
    const int half      = tid >> 7;            // 0 or 1: which 12 members
    const int out_gidx  = blockIdx.x * 128 + out_local;
    const int nout      = 2 * T_ * NG_ * NG_;  // 250000
    const bool valid    = out_gidx < nout;

    float acc = 0.0f;
    int j = 0, i = 0;
    if (valid) {
        j = out_gidx % NG_;
        i = (out_gidx / NG_) % NG_;
        const int t = (out_gidx / (NG_ * NG_)) % T_;
        const int f = out_gidx / (T_ * NG_ * NG_);

        const float* __restrict__ base = f ? c2 : c1;
        const int   ixN = s_ix[i] * NY_;
        const float fx  = s_fx[i];
        const float fx1 = 1.0f - fx;
        const int   m0  = half * (M_ / 2);

        #pragma unroll
        for (int k = 0; k < M_ / 2; k++) {
            const int m  = m0 + k;
            const int iy = s_iy[m * NG_ + j];
            const float e0 = s_e0[m * NG_ + j];
            const float e1 = s_e1[m * NG_ + j];
            const float* __restrict__ p0 =
                base + (m * TS_ + (int)s_ti[t * M_ + m]) * (NX_*NY_) + ixN + iy;
            float a00 = __ldg(p0);
            float a01 = __ldg(p0 + 1);
            float a10 = __ldg(p0 + NY_);
            float a11 = __ldg(p0 + NY_ + 1);
            acc += (a00 * fx1 + a10 * fx) * e0 + (a01 * fx1 + a11 * fx) * e1;
        }
    }

    if (half == 1) s_part[out_local] = acc;
    __syncthreads();

    if (valid && half == 0) {
        const int f = out_gidx / (T_ * NG_ * NG_);
        float v = (acc + s_part[out_local]) * s_mx[i];
        if (f == 0 && j == 0)       v = __ldg(cut_p);
        if (f == 1 && j == NG_ - 1) v = __ldg(nit_p);
        out[out_gidx] = v;
    }
}

extern "C" void kernel_launch(void* const* d_in, const int* in_sizes, int n_in,
                              void* d_out, int out_size)
{
    const float* c1    = (const float*)d_in[0];
    const float* c2    = (const float*)d_in[1];
    const float* params= (const float*)d_in[2];
    const float* src_y = (const float*)d_in[3];
    const float* stl   = (const float*)d_in[4];
    const float* Wq    = (const float*)d_in[5];
    const float* bq    = (const float*)d_in[6];
    const float* Wk    = (const float*)d_in[7];
    const float* bk    = (const float*)d_in[8];
    const float* lyt   = (const float*)d_in[9];
    const float* cut   = (const float*)d_in[10];
    const float* nit   = (const float*)d_in[11];
    float* out = (float*)d_out;

    setup_kernel<<<1, 1024>>>(params, src_y, stl, Wq, bq, Wk, bk, lyt, cut, nit);

    const int nout = 2 * T_ * NG_ * NG_;        // 250000 outputs
    const int blocks = (nout + 127) / 128;      // 128 outputs per 256-thread block
    gather_kernel<<<blocks, 256>>>(c1, c2, cut, nit, out);
}

// round 15
// speedup vs baseline: 1.1534x; 1.0478x over previous
#include <cuda_runtime.h>
#include <math.h>

#define M_   24
#define TS_  60
#define NX_  192
#define NY_  192
#define NG_  50
#define T_   50
#define HD_  32   // H*D
#define H_   4
#define D_   8

// Compact tables: setup_kernel -> gather_kernel (~14 KB)
__device__ float g_e0[M_ * NG_];     // w*my*(1-fy)
__device__ float g_e1[M_ * NG_];     // w*my*fy
__device__ short g_iy[M_ * NG_];
__device__ unsigned char g_ti[T_ * M_];
__device__ int   g_ix[NG_];
__device__ float g_fx[NG_];
__device__ float g_mx[NG_];

// jnp.linspace(0,100,192): delta = 100/191 (f32), endpoint forced exact.
__device__ __forceinline__ float gridx(int k) {
    return (k == NX_ - 1) ? 100.0f : (float)k * (100.0f / 191.0f);
}

__global__ __launch_bounds__(1024)
void setup_kernel(const float* __restrict__ params,
                  const float* __restrict__ src_y,
                  const float* __restrict__ stl,
                  const float* __restrict__ Wq,
                  const float* __restrict__ bq,
                  const float* __restrict__ Wk,
                  const float* __restrict__ bk,
                  const float* __restrict__ lyt_p,
                  const float* __restrict__ cut_p,
                  const float* __restrict__ nit_p)
{
    __shared__ __align__(16) float s_y[M_ * NY_];
    __shared__ float s_Wq[3*HD_], s_Wk[3*HD_], s_bq[HD_], s_bk[HD_], s_Q[HD_];
    __shared__ float s_ly[M_], s_cu[M_], s_ni[M_], s_scale[M_];
    __shared__ float s_logits[M_][H_];
    __shared__ float s_sm[H_][M_];
    __shared__ float s_w[M_];

    const int tid = threadIdx.x;
    const float lyt = __ldg(lyt_p);
    const float t_ly = (lyt - 30.0f) / 90.0f;
    const float t_cu = __ldg(cut_p) / 0.0029f;
    const float t_ni = __ldg(nit_p) / 0.0018f;

    // ---- phase 0: stage inputs, maximum MLP ----
    {
        const float4* sy4 = reinterpret_cast<const float4*>(src_y);
        float4* dy4 = reinterpret_cast<float4*>(s_y);
        for (int p = tid; p < (M_ * NY_) / 4; p += 1024)
            dy4[p] = __ldg(sy4 + p);
    }
    if (tid < 3 * HD_) { s_Wq[tid] = __ldg(Wq + tid); s_Wk[tid] = __ldg(Wk + tid); }
    else if (tid >= 128 && tid < 128 + HD_) {
        int k = tid - 128;
        s_bq[k] = __ldg(bq + k); s_bk[k] = __ldg(bk + k);
    }
    else if (tid >= 192 && tid < 192 + M_) {
        int m = tid - 192;
        float lys = __ldg(params + 3*m + 0);
        s_ly[m] = (lys - 30.0f) / 90.0f;
        s_cu[m] = __ldg(params + 3*m + 1) / 0.0029f;
        s_ni[m] = __ldg(params + 3*m + 2) / 0.0018f;
        s_scale[m] = lyt / lys;
    }
    __syncthreads();

    // ---- phase 1: Q vector ----
    if (tid < HD_)
        s_Q[tid] = t_ly*s_Wq[tid] + t_cu*s_Wq[HD_+tid] + t_ni*s_Wq[2*HD_+tid] + s_bq[tid];
    __syncthreads();

    // ---- phase 2: logits (m,h) ----
    if (tid < M_ * H_) {
        int m = tid / H_, h = tid % H_;
        float acc = 0.0f;
        #pragma unroll
        for (int d = 0; d < D_; d++) {
            int k = h*D_ + d;
            float Kv = s_ly[m]*s_Wk[k] + s_cu[m]*s_Wk[HD_+k] + s_ni[m]*s_Wk[2*HD_+k] + s_bk[k];
            acc += Kv * s_Q[k];
        }
        s_logits[m][h] = acc * (1.0f / sqrtf((float)D_));
    }
    __syncthreads();

    // ---- phase 3: softmax per head ----
    if (tid < H_) {
        int h = tid;
        float mx = -1e30f;
        for (int m = 0; m < M_; m++) mx = fmaxf(mx, s_logits[m][h]);
        float s = 0.0f;
        for (int m = 0; m < M_; m++) s += expf(s_logits[m][h] - mx);
        for (int m = 0; m < M_; m++) s_sm[h][m] = expf(s_logits[m][h] - mx) / s;
    }
    __syncthreads();

    // ---- phase 4: weights, warp 0 shfl reductions ----
    if (tid < 32) {
        int m = tid;
        float swv = 0.0f, attn = 0.0f;
        if (m < M_) {
            float d2 = ((s_ly[m]-t_ly)*(s_ly[m]-t_ly) +
                        (s_cu[m]-t_cu)*(s_cu[m]-t_cu) +
                        (s_ni[m]-t_ni)*(s_ni[m]-t_ni)) / (0.2f*0.2f);
            swv = expf(-d2 * 0.5f);
            attn = (s_sm[0][m] + s_sm[1][m] + s_sm[2][m] + s_sm[3][m]) * 0.25f;
        }
        float ssum = swv;
        #pragma unroll
        for (int o = 16; o > 0; o >>= 1) ssum += __shfl_xor_sync(0xffffffff, ssum, o);
        float wa = attn * (swv / (ssum + 1e-12f));
        float wsum = wa;
        #pragma unroll
        for (int o = 16; o > 0; o >>= 1) wsum += __shfl_xor_sync(0xffffffff, wsum, o);
        if (m < M_) s_w[m] = wa / (wsum + 1e-12f);
    }
    __syncthreads();

    // ---- phase 5: all tables in parallel ----
    if (tid >= 512 && tid < 512 + NG_) {
        int i = tid - 512;
        float q = (i == NG_-1) ? 100.0f : (float)i * (100.0f / 49.0f);
        int lo = 0, hi = NX_;
        while (lo < hi) { int mid = (lo + hi) >> 1; if (gridx(mid) <= q) lo = mid + 1; else hi = mid; }
        int idx = min(max(lo - 1, 0), NX_ - 2);
        float g0 = gridx(idx), g1 = gridx(idx + 1);
        g_ix[i] = idx;
        g_fx[i] = (q - g0) / (g1 - g0);
        g_mx[i] = (q >= 0.0f && q <= 100.0f) ? 1.0f : 0.0f;
    }
    if (tid >= 576 && tid < 576 + 400) {
        for (int p = tid - 576; p < T_ * M_; p += 400) {
            int t = p / M_, m = p % M_;
            float tv = (t == T_-1) ? 200.0f : (float)t * (200.0f / 49.0f);
            float r = rintf(tv / __ldg(stl + m) * (float)(TS_ - 1));
            g_ti[t * M_ + m] = (unsigned char)min(max((int)r, 0), TS_ - 1);
        }
    }
    if (tid < 512) {
        for (int p = tid; p < M_ * NG_; p += 512) {
            int m = p / NG_, j = p % NG_;
            float q  = (float)j / 49.0f * lyt;
            float sc = s_scale[m];
            const float* ys = s_y + m * NY_;
            int lo = 0, hi = NY_;
            while (lo < hi) { int mid = (lo + hi) >> 1; if (ys[mid]*sc <= q) lo = mid + 1; else hi = mid; }
            int idx = min(max(lo - 1, 0), NY_ - 2);
            float gy0 = ys[idx] * sc, gy1 = ys[idx + 1] * sc;
            float fy = (q - gy0) / (gy1 - gy0);
            float inb = (q >= ys[0]*sc && q <= ys[NY_-1]*sc) ? 1.0f : 0.0f;
            float wm = s_w[m] * inb;
            g_iy[p] = (short)idx;
            g_e0[p] = wm * (1.0f - fy);
            g_e1[p] = wm * fy;
        }
    }
}

// Round-10 gather (measured best: 34.3us) + PDL grid-dependency sync.
__global__ __launch_bounds__(256)
void gather_kernel(const float* __restrict__ c1,
                   const float* __restrict__ c2,
                   const float* __restrict__ cut_p,
                   const float* __restrict__ nit_p,
                   float* __restrict__ out)
{
    __shared__ float s_e0[M_ * NG_];
    __shared__ float s_e1[M_ * NG_];
    __shared__ short s_iy[M_ * NG_];
    __shared__ unsigned char s_ti[T_ * M_];
    __shared__ int   s_ix[NG_];
    __shared__ float s_fx[NG_];
    __shared__ float s_mx[NG_];

    const int tid = threadIdx.x;

    // Wait for setup_kernel's tables (our launch/prologue overlapped with it).
    cudaGridDependencySynchronize();

    for (int p = tid; p < M_ * NG_; p += 256) {
        s_e0[p] = g_e0[p];
        s_e1[p] = g_e1[p];
        s_iy[p] = g_iy[p];
        s_ti[p] = g_ti[p];          // T_*M_ == M_*NG_ == 1200
    }
    if (tid < NG_) { s_ix[tid] = g_ix[tid]; s_fx[tid] = g_fx[tid]; s_mx[tid] = g_mx[tid]; }
    __syncthreads();

    const int gidx = blockIdx.x * 256 + tid;
    const int nthreads = 2 * T_ * NG_ * NG_;   // 250000
    if (gidx >= nthreads) return;

    const int j = gidx % NG_;
    const int i = (gidx / NG_) % NG_;
    const int t = (gidx / (NG_ * NG_)) % T_;
    const int f = gidx / (T_ * NG_ * NG_);

    const float* __restrict__ base = f ? c2 : c1;
    const int   ixN = s_ix[i] * NY_;
    const float fx  = s_fx[i];
    const float fx1 = 1.0f - fx;

    float acc = 0.0f;
#pragma unroll 8
    for (int m = 0; m < M_; m++) {
        const int   iy = s_iy[m * NG_ + j];
        const float e0 = s_e0[m * NG_ + j];
        const float e1 = s_e1[m * NG_ + j];
        const float* __restrict__ p0 =
            base + (m * TS_ + (int)s_ti[t * M_ + m]) * (NX_*NY_) + ixN + iy;
        float a00 = __ldg(p0);
        float a01 = __ldg(p0 + 1);
        float a10 = __ldg(p0 + NY_);
        float a11 = __ldg(p0 + NY_ + 1);
        acc += (a00 * fx1 + a10 * fx) * e0 + (a01 * fx1 + a11 * fx) * e1;
    }
    float v = acc * s_mx[i];
    if (f == 0 && j == 0)       v = __ldg(cut_p);
    if (f == 1 && j == NG_ - 1) v = __ldg(nit_p);

    out[gidx] = v;
}

extern "C" void kernel_launch(void* const* d_in, const int* in_sizes, int n_in,
                              void* d_out, int out_size)
{
    const float* c1    = (const float*)d_in[0];
    const float* c2    = (const float*)d_in[1];
    const float* params= (const float*)d_in[2];
    const float* src_y = (const float*)d_in[3];
    const float* stl   = (const float*)d_in[4];
    const float* Wq    = (const float*)d_in[5];
    const float* bq    = (const float*)d_in[6];
    const float* Wk    = (const float*)d_in[7];
    const float* bk    = (const float*)d_in[8];
    const float* lyt   = (const float*)d_in[9];
    const float* cut   = (const float*)d_in[10];
    const float* nit   = (const float*)d_in[11];
    float* out = (float*)d_out;

    setup_kernel<<<1, 1024>>>(params, src_y, stl, Wq, bq, Wk, bk, lyt, cut, nit);

    const int nthreads = 2 * T_ * NG_ * NG_;   // 250000
    const int blocks = (nthreads + 255) / 256;

    // PDL launch: gather grid launches while setup runs; the in-kernel
    // cudaGridDependencySynchronize() gates consumption of the tables.
    cudaLaunchConfig_t cfg = {};
    cfg.gridDim  = dim3((unsigned)blocks, 1, 1);
    cfg.blockDim = dim3(256, 1, 1);
    cfg.dynamicSmemBytes = 0;
    cfg.stream = 0;   // legacy default stream (the one the harness captures)
    cudaLaunchAttribute attrs[1];
    attrs[0].id = cudaLaunchAttributeProgrammaticStreamSerialization;
    attrs[0].val.programmaticStreamSerializationAllowed = 1;
    cfg.attrs = attrs;
    cfg.numAttrs = 1;
    cudaLaunchKernelEx(&cfg, gather_kernel, c1, c2, cut, nit, out);
}

// round 16
// speedup vs baseline: 1.1552x; 1.0015x over previous
#include <cuda_runtime.h>
#include <math.h>

#define M_   24
#define TS_  60
#define NX_  192
#define NY_  192
#define NG_  50
#define T_   50
#define HD_  32   // H*D
#define H_   4
#define D_   8

// Compact tables: setup_kernel -> gather_kernel (~14 KB)
__device__ float g_e0[M_ * NG_];     // w*my*(1-fy)
__device__ float g_e1[M_ * NG_];     // w*my*fy
__device__ short g_iy[M_ * NG_];
__device__ unsigned char g_ti[T_ * M_];
__device__ int   g_ix[NG_];
__device__ float g_fx[NG_];
__device__ float g_mx[NG_];

// jnp.linspace(0,100,192): delta = 100/191 (f32), endpoint forced exact.
__device__ __forceinline__ float gridx(int k) {
    return (k == NX_ - 1) ? 100.0f : (float)k * (100.0f / 191.0f);
}

__device__ __forceinline__ void prefetch_l2(const void* p) {
    asm volatile("prefetch.global.L2 [%0];" :: "l"(p));
}

__global__ __launch_bounds__(1024)
void setup_kernel(const float* __restrict__ params,
                  const float* __restrict__ src_y,
                  const float* __restrict__ stl,
                  const float* __restrict__ Wq,
                  const float* __restrict__ bq,
                  const float* __restrict__ Wk,
                  const float* __restrict__ bk,
                  const float* __restrict__ lyt_p,
                  const float* __restrict__ cut_p,
                  const float* __restrict__ nit_p)
{
    __shared__ __align__(16) float s_y[M_ * NY_];
    __shared__ float s_Wq[3*HD_], s_Wk[3*HD_], s_bq[HD_], s_bk[HD_], s_Q[HD_];
    __shared__ float s_ly[M_], s_cu[M_], s_ni[M_], s_scale[M_];
    __shared__ float s_logits[M_][H_];
    __shared__ float s_sm[H_][M_];
    __shared__ float s_w[M_];

    const int tid = threadIdx.x;
    const float lyt = __ldg(lyt_p);
    const float t_ly = (lyt - 30.0f) / 90.0f;
    const float t_cu = __ldg(cut_p) / 0.0029f;
    const float t_ni = __ldg(nit_p) / 0.0018f;

    // ---- phase 0: stage inputs, maximum MLP ----
    {
        const float4* sy4 = reinterpret_cast<const float4*>(src_y);
        float4* dy4 = reinterpret_cast<float4*>(s_y);
        for (int p = tid; p < (M_ * NY_) / 4; p += 1024)
            dy4[p] = __ldg(sy4 + p);
    }
    if (tid < 3 * HD_) { s_Wq[tid] = __ldg(Wq + tid); s_Wk[tid] = __ldg(Wk + tid); }
    else if (tid >= 128 && tid < 128 + HD_) {
        int k = tid - 128;
        s_bq[k] = __ldg(bq + k); s_bk[k] = __ldg(bk + k);
    }
    else if (tid >= 192 && tid < 192 + M_) {
        int m = tid - 192;
        float lys = __ldg(params + 3*m + 0);
        s_ly[m] = (lys - 30.0f) / 90.0f;
        s_cu[m] = __ldg(params + 3*m + 1) / 0.0029f;
        s_ni[m] = __ldg(params + 3*m + 2) / 0.0018f;
        s_scale[m] = lyt / lys;
    }
    __syncthreads();

    // ---- phase 1: Q vector ----
    if (tid < HD_)
        s_Q[tid] = t_ly*s_Wq[tid] + t_cu*s_Wq[HD_+tid] + t_ni*s_Wq[2*HD_+tid] + s_bq[tid];
    __syncthreads();

    // ---- phase 2: logits (m,h) ----
    if (tid < M_ * H_) {
        int m = tid / H_, h = tid % H_;
        float acc = 0.0f;
        #pragma unroll
        for (int d = 0; d < D_; d++) {
            int k = h*D_ + d;
            float Kv = s_ly[m]*s_Wk[k] + s_cu[m]*s_Wk[HD_+k] + s_ni[m]*s_Wk[2*HD_+k] + s_bk[k];
            acc += Kv * s_Q[k];
        }
        s_logits[m][h] = acc * (1.0f / sqrtf((float)D_));
    }
    __syncthreads();

    // ---- phase 3: softmax per head ----
    if (tid < H_) {
        int h = tid;
        float mx = -1e30f;
        for (int m = 0; m < M_; m++) mx = fmaxf(mx, s_logits[m][h]);
        float s = 0.0f;
        for (int m = 0; m < M_; m++) s += expf(s_logits[m][h] - mx);
        for (int m = 0; m < M_; m++) s_sm[h][m] = expf(s_logits[m][h] - mx) / s;
    }
    __syncthreads();

    // ---- phase 4: weights, warp 0 shfl reductions ----
    if (tid < 32) {
        int m = tid;
        float swv = 0.0f, attn = 0.0f;
        if (m < M_) {
            float d2 = ((s_ly[m]-t_ly)*(s_ly[m]-t_ly) +
                        (s_cu[m]-t_cu)*(s_cu[m]-t_cu) +
                        (s_ni[m]-t_ni)*(s_ni[m]-t_ni)) / (0.2f*0.2f);
            swv = expf(-d2 * 0.5f);
            attn = (s_sm[0][m] + s_sm[1][m] + s_sm[2][m] + s_sm[3][m]) * 0.25f;
        }
        float ssum = swv;
        #pragma unroll
        for (int o = 16; o > 0; o >>= 1) ssum += __shfl_xor_sync(0xffffffff, ssum, o);
        float wa = attn * (swv / (ssum + 1e-12f));
        float wsum = wa;
        #pragma unroll
        for (int o = 16; o > 0; o >>= 1) wsum += __shfl_xor_sync(0xffffffff, wsum, o);
        if (m < M_) s_w[m] = wa / (wsum + 1e-12f);
    }
    __syncthreads();

    // ---- phase 5: all tables in parallel ----
    if (tid >= 512 && tid < 512 + NG_) {
        int i = tid - 512;
        float q = (i == NG_-1) ? 100.0f : (float)i * (100.0f / 49.0f);
        int lo = 0, hi = NX_;
        while (lo < hi) { int mid = (lo + hi) >> 1; if (gridx(mid) <= q) lo = mid + 1; else hi = mid; }
        int idx = min(max(lo - 1, 0), NX_ - 2);
        float g0 = gridx(idx), g1 = gridx(idx + 1);
        g_ix[i] = idx;
        g_fx[i] = (q - g0) / (g1 - g0);
        g_mx[i] = (q >= 0.0f && q <= 100.0f) ? 1.0f : 0.0f;
    }
    if (tid >= 576 && tid < 576 + 400) {
        for (int p = tid - 576; p < T_ * M_; p += 400) {
            int t = p / M_, m = p % M_;
            float tv = (t == T_-1) ? 200.0f : (float)t * (200.0f / 49.0f);
            float r = rintf(tv / __ldg(stl + m) * (float)(TS_ - 1));
            g_ti[t * M_ + m] = (unsigned char)min(max((int)r, 0), TS_ - 1);
        }
    }
    if (tid < 512) {
        for (int p = tid; p < M_ * NG_; p += 512) {
            int m = p / NG_, j = p % NG_;
            float q  = (float)j / 49.0f * lyt;
            float sc = s_scale[m];
            const float* ys = s_y + m * NY_;
            int lo = 0, hi = NY_;
            while (lo < hi) { int mid = (lo + hi) >> 1; if (ys[mid]*sc <= q) lo = mid + 1; else hi = mid; }
            int idx = min(max(lo - 1, 0), NY_ - 2);
            float gy0 = ys[idx] * sc, gy1 = ys[idx + 1] * sc;
            float fy = (q - gy0) / (gy1 - gy0);
            float inb = (q >= ys[0]*sc && q <= ys[NY_-1]*sc) ? 1.0f : 0.0f;
            float wm = s_w[m] * inb;
            g_iy[p] = (short)idx;
            g_e0[p] = wm * (1.0f - fy);
            g_e1[p] = wm * fy;
        }
    }

    cudaTriggerProgrammaticLaunchCompletion();
}

// Gather + pre-sync L2 prefetch of all needed field rows.
__global__ __launch_bounds__(256)
void gather_kernel(const float* __restrict__ c1,
                   const float* __restrict__ c2,
                   const float* __restrict__ stl,
                   const float* __restrict__ cut_p,
                   const float* __restrict__ nit_p,
                   float* __restrict__ out)
{
    __shared__ float s_e0[M_ * NG_];
    __shared__ float s_e1[M_ * NG_];
    __shared__ short s_iy[M_ * NG_];
    __shared__ unsigned char s_ti[T_ * M_];
    __shared__ int   s_ix[NG_];
    __shared__ float s_fx[NG_];
    __shared__ float s_mx[NG_];

    const int tid = threadIdx.x;
    const int gidx = blockIdx.x * 256 + tid;
    const int nthreads = 2 * T_ * NG_ * NG_;   // 250000
    const bool valid = gidx < nthreads;

    int j = 0, i = 0, t = 0, f = 0;
    if (valid) {
        j = gidx % NG_;
        i = (gidx / NG_) % NG_;
        t = (gidx / (NG_ * NG_)) % T_;
        f = gidx / (T_ * NG_ * NG_);
    }

    // ---- PRE-SYNC PREFETCH: row addresses need no setup tables ----
    // ix: searchsorted on the uniform x grid (pure register arithmetic).
    // ti: from stl (direct kernel input).
    // Threads with j<48 each prefetch one (m, row) pair: m=j>>1, row=ix+(j&1).
    if (valid && j < 2 * M_) {
        const int m    = j >> 1;
        const int rsel = j & 1;
        // inline ix (identical semantics to setup's search)
        float q = (i == NG_-1) ? 100.0f : (float)i * (100.0f / 49.0f);
        int lo = 0, hi = NX_;
        #pragma unroll
        for (int it = 0; it < 8; it++) {
            int mid = (lo + hi) >> 1;
            if (lo < hi) { if (gridx(mid) <= q) lo = mid + 1; else hi = mid; }
        }
        int ix = min(max(lo - 1, 0), NX_ - 2);
        // inline ti[t][m]
        float tv = (t == T_-1) ? 200.0f : (float)t * (200.0f / 49.0f);
        float r = rintf(tv / __ldg(stl + m) * (float)(TS_ - 1));
        int ti = min(max((int)r, 0), TS_ - 1);

        const float* __restrict__ base = f ? c2 : c1;
        const float* row = base + (m * TS_ + ti) * (NX_*NY_) + (ix + rsel) * NY_;
        const char* rp = (const char*)row;
        #pragma unroll
        for (int l = 0; l < 6; l++)                    // 192 floats = 6 x 128B
            prefetch_l2(rp + l * 128);
    }

    // ---- gate on setup tables (launch + prefetch overlapped with setup) ----
    cudaGridDependencySynchronize();

    for (int p = tid; p < M_ * NG_; p += 256) {
        s_e0[p] = g_e0[p];
        s_e1[p] = g_e1[p];
        s_iy[p] = g_iy[p];
        s_ti[p] = g_ti[p];          // T_*M_ == M_*NG_ == 1200
    }
    if (tid < NG_) { s_ix[tid] = g_ix[tid]; s_fx[tid] = g_fx[tid]; s_mx[tid] = g_mx[tid]; }
    __syncthreads();

    if (!valid) return;

    const float* __restrict__ base = f ? c2 : c1;
    const int   ixN = s_ix[i] * NY_;
    const float fx  = s_fx[i];
    const float fx1 = 1.0f - fx;

    float acc = 0.0f;
#pragma unroll 8
    for (int m = 0; m < M_; m++) {
        const int   iy = s_iy[m * NG_ + j];
        const float e0 = s_e0[m * NG_ + j];
        const float e1 = s_e1[m * NG_ + j];
        const float* __restrict__ p0 =
            base + (m * TS_ + (int)s_ti[t * M_ + m]) * (NX_*NY_) + ixN + iy;
        float a00 = __ldg(p0);
        float a01 = __ldg(p0 + 1);
        float a10 = __ldg(p0 + NY_);
        float a11 = __ldg(p0 + NY_ + 1);
        acc += (a00 * fx1 + a10 * fx) * e0 + (a01 * fx1 + a11 * fx) * e1;
    }
    float v = acc * s_mx[i];
    if (f == 0 && j == 0)       v = __ldg(cut_p);
    if (f == 1 && j == NG_ - 1) v = __ldg(nit_p);

    out[gidx] = v;
}

extern "C" void kernel_launch(void* const* d_in, const int* in_sizes, int n_in,
                              void* d_out, int out_size)
{
    const float* c1    = (const float*)d_in[0];
    const float* c2    = (const float*)d_in[1];
    const float* params= (const float*)d_in[2];
    const float* src_y = (const float*)d_in[3];
    const float* stl   = (const float*)d_in[4];
    const float* Wq    = (const float*)d_in[5];
    const float* bq    = (const float*)d_in[6];
    const float* Wk    = (const float*)d_in[7];
    const float* bk    = (const float*)d_in[8];
    const float* lyt   = (const float*)d_in[9];
    const float* cut   = (const float*)d_in[10];
    const float* nit   = (const float*)d_in[11];
    float* out = (float*)d_out;

    setup_kernel<<<1, 1024>>>(params, src_y, stl, Wq, bq, Wk, bk, lyt, cut, nit);

    const int nthreads = 2 * T_ * NG_ * NG_;   // 250000
    const int blocks = (nthreads + 255) / 256;

    // PDL launch: gather grid launches while setup runs; pre-sync prefetches
    // start the DRAM->L2 fill immediately; griddepsync gates table reads.
    cudaLaunchConfig_t cfg = {};
    cfg.gridDim  = dim3((unsigned)blocks, 1, 1);
    cfg.blockDim = dim3(256, 1, 1);
    cfg.dynamicSmemBytes = 0;
    cfg.stream = 0;
    cudaLaunchAttribute attrs[1];
    attrs[0].id = cudaLaunchAttributeProgrammaticStreamSerialization;
    attrs[0].val.programmaticStreamSerializationAllowed = 1;
    cfg.attrs = attrs;
    cfg.numAttrs = 1;
    cudaLaunchKernelEx(&cfg, gather_kernel, c1, c2, stl, cut, nit, out);
}